// round 3
// baseline (speedup 1.0000x reference)
#include <cuda_runtime.h>

#define N_AGENTS 4096
#define TPB 256
#define JPT 16          // 4096 / 256 candidates per thread
#define TOPK 32
#define W2T_LD 132      // padded leading dim for transposed W2 in smem
#define NBINS 64
#define HIST_LD 264     // bytes per bin row: 256 thread columns + 8 pad
#define CAND_CAP 256
#define BIN_BIAS 226
#define SMEM_BYTES 73472

// ---- dynamic smem layout (byte offsets) ----
#define OFF_W2T     0        // f32[64*132]   33792 B
#define OFF_H1S2    33792    // f32[64*64]    16384 B  (h duplicated pairs {v,v})
#define OFF_HIST    50176    // u8 [64*264]   16896 B
#define OFF_CAND    67072    // u64[256]       2048 B
#define OFF_TOT     69120    // i32[64]         256 B
#define OFF_XK      69376    // f32[160]        640 B
#define OFF_W1S     70016    // f32[320]       1280 B
#define OFF_B1S     71296    // f32[64]         256 B
#define OFF_MASK    71552    // f32[32]         128 B
#define OFF_SEL     71680    // u32[32]         128 B
#define OFF_FEAT    71808    // f32[132]        528 B
#define OFF_Z1      72336    // f32[64]
#define OFF_Z2      72592    // f32[128]
#define OFF_Z3      73104    // f32[64]
#define OFF_Z4      73360    // f32[4]
#define OFF_CNT     73376    // i32
#define OFF_T       73380    // i32

__device__ __forceinline__ int dd_bin(float dd) {
    int b = (int)(__float_as_uint(dd) >> 22) - BIN_BIAS;
    b = b < 0 ? 0 : b;
    return b > (NBINS - 1) ? (NBINS - 1) : b;
}

__global__ __launch_bounds__(TPB)
void controller_kernel(
    const float4* __restrict__ states4,   // [N,4]
    const float*  __restrict__ goals,     // [N,2]
    const float*  __restrict__ W1,  const float* __restrict__ b1,
    const float*  __restrict__ W2,  const float* __restrict__ b2,
    const float*  __restrict__ Wd1, const float* __restrict__ bd1,
    const float*  __restrict__ Wd2, const float* __restrict__ bd2,
    const float*  __restrict__ Wd3, const float* __restrict__ bd3,
    const float*  __restrict__ Wd4, const float* __restrict__ bd4,
    float* __restrict__ out)              // [N,2]
{
    extern __shared__ __align__(16) char smem[];
    float*              w2t     = (float*)(smem + OFF_W2T);
    float*              h1s2    = (float*)(smem + OFF_H1S2);
    unsigned char*      hist    = (unsigned char*)(smem + OFF_HIST);
    unsigned long long* candbuf = (unsigned long long*)(smem + OFF_CAND);
    int*                tot     = (int*)(smem + OFF_TOT);
    float*              xkflat  = (float*)(smem + OFF_XK);
    float*              W1s     = (float*)(smem + OFF_W1S);
    float*              b1s     = (float*)(smem + OFF_B1S);
    float*              masksh  = (float*)(smem + OFF_MASK);
    unsigned*           selsh   = (unsigned*)(smem + OFF_SEL);
    float*              featsh  = (float*)(smem + OFF_FEAT);
    float*              z1s     = (float*)(smem + OFF_Z1);
    float*              z2s     = (float*)(smem + OFF_Z2);
    float*              z3s     = (float*)(smem + OFF_Z3);
    float*              z4s     = (float*)(smem + OFF_Z4);
    int*                cntp    = (int*)(smem + OFF_CNT);
    int*                Tsh     = (int*)(smem + OFF_T);

    const int tid  = threadIdx.x;
    const int i    = blockIdx.x;
    const int lane = tid & 31;
    const int wid  = tid >> 5;

    const float4 si = states4[i];

    // ---- stage weights + zero histogram + distance pass (all before 1st barrier) ----
    {
        int* histw = (int*)hist;
        #pragma unroll
        for (int t = tid; t < (NBINS * HIST_LD) / 4; t += TPB) histw[t] = 0;
    }
    if (tid == 0) *cntp = 0;
    for (int t = tid; t < 320; t += TPB) W1s[t] = W1[t];
    if (tid < 64) b1s[tid] = b1[tid];
    for (int idx = tid; idx < 8192; idx += TPB) {
        int o = idx >> 6, c = idx & 63;          // coalesced global read
        w2t[c * W2T_LD + o] = W2[idx];
    }

    float ddv[JPT];
    {
        const float2* stxy = (const float2*)states4;   // xy at even float2 slots
        #pragma unroll
        for (int k = 0; k < JPT; k++) {
            int j = tid + (k << 8);
            float2 sj = __ldg(&stxy[2 * j]);
            float dx = si.x - sj.x;
            float dy = si.y - sj.y;
            ddv[k] = dx * dx + dy * dy + 1e-4f;
        }
    }
    __syncthreads();

    // ---- histogram build: each thread owns byte column `tid` (no races) ----
    #pragma unroll
    for (int k = 0; k < JPT; k++) {
        int b = dd_bin(ddv[k]);
        hist[b * HIST_LD + tid]++;
    }
    __syncthreads();

    // ---- per-bin totals (dp4a byte sums, 4 threads per bin) ----
    {
        int b = tid >> 2, q = tid & 3;
        const int* row = (const int*)(hist + b * HIST_LD);
        int start = q * 17;
        int end   = start + 17; if (end > 66) end = 66;
        int s = 0;
        for (int w = start; w < end; w++) s = __dp4a(row[w], 0x01010101, s);
        s += __shfl_xor_sync(0xffffffffu, s, 1);
        s += __shfl_xor_sync(0xffffffffu, s, 2);
        if (q == 0) tot[b] = s;
    }
    __syncthreads();

    // ---- warp 0: inclusive scan over 64 bins, find threshold bin T ----
    if (wid == 0) {
        int a = tot[lane];
        int c = tot[lane + 32];
        int sa = a;
        #pragma unroll
        for (int off = 1; off < 32; off <<= 1) {
            int t = __shfl_up_sync(0xffffffffu, sa, off);
            if (lane >= off) sa += t;
        }
        int suma = __shfl_sync(0xffffffffu, sa, 31);
        int sc = c;
        #pragma unroll
        for (int off = 1; off < 32; off <<= 1) {
            int t = __shfl_up_sync(0xffffffffu, sc, off);
            if (lane >= off) sc += t;
        }
        sc += suma;
        unsigned ba = __ballot_sync(0xffffffffu, sa >= TOPK);
        unsigned bc = __ballot_sync(0xffffffffu, sc >= TOPK);
        int T = ba ? (__ffs(ba) - 1) : (32 + __ffs(bc) - 1);
        if (lane == 0) *Tsh = T;
    }
    __syncthreads();
    const int T = *Tsh;

    // ---- compact candidates with bin <= T (warp-aggregated) ----
    #pragma unroll
    for (int k = 0; k < JPT; k++) {
        int j = tid + (k << 8);
        bool act = (dd_bin(ddv[k]) <= T);
        unsigned m = __ballot_sync(0xffffffffu, act);
        if (m) {
            int leader = __ffs(m) - 1;
            int base = 0;
            if (lane == leader) base = atomicAdd(cntp, __popc(m));
            base = __shfl_sync(0xffffffffu, base, leader);
            if (act) {
                int pos = base + __popc(m & ((1u << lane) - 1u));
                if (pos < CAND_CAP) {
                    float d = sqrtf(ddv[k]);
                    candbuf[pos] = (((unsigned long long)__float_as_uint(d)) << 32) | (unsigned)j;
                }
            }
        }
    }
    __syncthreads();

    // ---- exact rank among candidates: top-32 by (d_bits, j), stable like lax.top_k ----
    {
        int M = *cntp; if (M > CAND_CAP) M = CAND_CAP;
        if (tid < M) {
            unsigned long long kt = candbuf[tid];
            int rank = 0;
            for (int c = 0; c < M; c++) rank += (candbuf[c] < kt);
            if (rank < TOPK) selsh[rank] = (unsigned)kt;   // low 32 bits = j
        }
    }
    __syncthreads();

    // ---- gather xk rows + obs mask + tail features ----
    if (tid < TOPK) {
        int j = (int)selsh[tid];
        float4 sj = states4[j];
        float dx = si.x - sj.x;
        float dy = si.y - sj.y;
        xkflat[tid * 5 + 0] = dx;
        xkflat[tid * 5 + 1] = dy;
        xkflat[tid * 5 + 2] = si.z - sj.z;
        xkflat[tid * 5 + 3] = si.w - sj.w;
        xkflat[tid * 5 + 4] = (j == i) ? 1.0f : 0.0f;
        masksh[tid] = (sqrtf(dx * dx + dy * dy) < 1.0f) ? 1.0f : 0.0f;
    }
    if (tid == 0) {
        float gx = goals[2 * i], gy = goals[2 * i + 1];
        featsh[128] = si.x - gx;
        featsh[129] = si.y - gy;
        featsh[130] = si.z;
        featsh[131] = si.w;
    }
    __syncthreads();

    // ---- conv1 5->64, store h duplicated as {v,v} pairs for f32x2 conv2 ----
    for (int idx = tid; idx < 2048; idx += TPB) {
        int o = idx >> 5, p = idx & 31;
        float acc = b1s[o];
        #pragma unroll
        for (int c = 0; c < 5; c++)
            acc = fmaf(W1s[o * 5 + c], xkflat[c * 32 + p], acc);
        acc = fmaxf(acc, 0.0f);
        ((float2*)h1s2)[(o << 5) + p] = make_float2(acc, acc);
    }
    __syncthreads();

    // ---- conv2 64->128 with packed f32x2 FMA + masked argmax ----
    {
        const int to = tid >> 3;           // o base = to*4   (0..31)
        const int tp = (tid & 7) << 2;     // p base          (0..28)
        unsigned long long accp[2][4];     // f32x2: [o-pair][p]
        #pragma unroll
        for (int op = 0; op < 2; op++)
            #pragma unroll
            for (int pp = 0; pp < 4; pp++) accp[op][pp] = 0ull;

        #pragma unroll 4
        for (int c = 0; c < 64; c++) {
            const ulonglong2 wv = *reinterpret_cast<const ulonglong2*>(
                &w2t[c * W2T_LD + (to << 2)]);                    // (w0,w1),(w2,w3)
            const ulonglong2 hv0 = *reinterpret_cast<const ulonglong2*>(
                &h1s2[(c << 6) + (tp << 1)]);                     // {h0,h0},{h1,h1}
            const ulonglong2 hv1 = *reinterpret_cast<const ulonglong2*>(
                &h1s2[(c << 6) + (tp << 1) + 4]);                 // {h2,h2},{h3,h3}
            unsigned long long hp[4] = {hv0.x, hv0.y, hv1.x, hv1.y};
            #pragma unroll
            for (int pp = 0; pp < 4; pp++) {
                asm("fma.rn.f32x2 %0, %1, %2, %0;" : "+l"(accp[0][pp]) : "l"(wv.x), "l"(hp[pp]));
                asm("fma.rn.f32x2 %0, %1, %2, %0;" : "+l"(accp[1][pp]) : "l"(wv.y), "l"(hp[pp]));
            }
        }

        float acc[4][4];
        #pragma unroll
        for (int pp = 0; pp < 4; pp++) {
            asm("mov.b64 {%0, %1}, %2;" : "=f"(acc[0][pp]), "=f"(acc[1][pp]) : "l"(accp[0][pp]));
            asm("mov.b64 {%0, %1}, %2;" : "=f"(acc[2][pp]), "=f"(acc[3][pp]) : "l"(accp[1][pp]));
        }

        float mk[4];
        #pragma unroll
        for (int pp = 0; pp < 4; pp++) mk[pp] = masksh[tp + pp];

        #pragma unroll
        for (int oo = 0; oo < 4; oo++) {
            int o = (to << 2) + oo;
            float bb = b2[o];
            float bv = 0.0f;
            int   bp = 0;
            #pragma unroll
            for (int pp = 0; pp < 4; pp++) {
                float v = fmaxf(acc[oo][pp] + bb, 0.0f) * mk[pp];
                if (pp == 0) { bv = v; bp = tp; }
                else if (v > bv) { bv = v; bp = tp + pp; }   // strict > keeps first index
            }
            #pragma unroll
            for (int off = 1; off < 8; off <<= 1) {
                float ov = __shfl_xor_sync(0xffffffffu, bv, off);
                int   op = __shfl_xor_sync(0xffffffffu, bp, off);
                if (ov > bv || (ov == bv && op < bp)) { bv = ov; bp = op; }
            }
            if ((tid & 7) == 0) featsh[o] = (float)bp;
        }
    }
    __syncthreads();

    // ---- MLP 132 -> 64 -> 128 -> 64 -> 4 ----
    for (int o = wid; o < 64; o += 8) {
        float s = 0.0f;
        for (int c = lane; c < 132; c += 32)
            s = fmaf(Wd1[o * 132 + c], featsh[c], s);
        #pragma unroll
        for (int off = 16; off; off >>= 1) s += __shfl_xor_sync(0xffffffffu, s, off);
        if (lane == 0) z1s[o] = fmaxf(s + bd1[o], 0.0f);
    }
    __syncthreads();

    for (int o = wid; o < 128; o += 8) {
        float s = 0.0f;
        #pragma unroll
        for (int c = lane; c < 64; c += 32)
            s = fmaf(Wd2[o * 64 + c], z1s[c], s);
        #pragma unroll
        for (int off = 16; off; off >>= 1) s += __shfl_xor_sync(0xffffffffu, s, off);
        if (lane == 0) z2s[o] = fmaxf(s + bd2[o], 0.0f);
    }
    __syncthreads();

    for (int o = wid; o < 64; o += 8) {
        float s = 0.0f;
        #pragma unroll
        for (int c = lane; c < 128; c += 32)
            s = fmaf(Wd3[o * 128 + c], z2s[c], s);
        #pragma unroll
        for (int off = 16; off; off >>= 1) s += __shfl_xor_sync(0xffffffffu, s, off);
        if (lane == 0) z3s[o] = fmaxf(s + bd3[o], 0.0f);
    }
    __syncthreads();

    if (wid < 4) {
        int o = wid;
        float s = 0.0f;
        #pragma unroll
        for (int c = lane; c < 64; c += 32)
            s = fmaf(Wd4[o * 64 + c], z3s[c], s);
        #pragma unroll
        for (int off = 16; off; off >>= 1) s += __shfl_xor_sync(0xffffffffu, s, off);
        if (lane == 0) z4s[o] = s + bd4[o];
    }
    __syncthreads();

    // ---- gains + control output ----
    if (tid == 0) {
        float k0 = 2.0f / (1.0f + expf(-z4s[0])) + 0.2f;
        float k1 = 2.0f / (1.0f + expf(-z4s[1])) + 0.2f;
        float k2 = 2.0f / (1.0f + expf(-z4s[2])) + 0.2f;
        float k3 = 2.0f / (1.0f + expf(-z4s[3])) + 0.2f;
        float rx = featsh[128], ry = featsh[129];
        float v2 = featsh[130], v3 = featsh[131];
        out[2 * i + 0] = -(k0 * rx + k1 * v2);
        out[2 * i + 1] = -(k2 * ry + k3 * v3);
    }
}

extern "C" void kernel_launch(void* const* d_in, const int* in_sizes, int n_in,
                              void* d_out, int out_size)
{
    (void)in_sizes; (void)n_in; (void)out_size;
    cudaFuncSetAttribute(controller_kernel,
                         cudaFuncAttributeMaxDynamicSharedMemorySize, SMEM_BYTES);
    controller_kernel<<<N_AGENTS, TPB, SMEM_BYTES>>>(
        (const float4*)d_in[0],  (const float*)d_in[1],
        (const float*)d_in[2],   (const float*)d_in[3],
        (const float*)d_in[4],   (const float*)d_in[5],
        (const float*)d_in[6],   (const float*)d_in[7],
        (const float*)d_in[8],   (const float*)d_in[9],
        (const float*)d_in[10],  (const float*)d_in[11],
        (const float*)d_in[12],  (const float*)d_in[13],
        (float*)d_out);
}

// round 5
// speedup vs baseline: 1.9214x; 1.9214x over previous
#include <cuda_runtime.h>

#define N_AGENTS 4096
#define TPB 256
#define JPT 16          // 4096/256 candidates per thread
#define TOPK 32
#define W2T_LD 132

// ---- static smem layout (byte offsets), with phase-disjoint aliases ----
#define OFF_W2T   0        // f32[64*132] 33792B   (dead after conv2)
#define OFF_Z1    0        //   alias: f32[64]     (post-conv2)
#define OFF_Z2    256      //   alias: f32[128]
#define OFF_Z3    768      //   alias: f32[64]
#define OFF_Z4    1024     //   alias: f32[4]
#define OFF_H1S   33792    // f32[64*32] 8192B     (conv phases)
#define OFF_SKEY  33792    //   alias: u64[256]    (selection merge, pre-conv1)
#define OFF_W1S   41984    // f32[320] 1280B
#define OFF_B1S   43264    // f32[64]  256B
#define OFF_B2S   43520    // f32[128] 512B
#define OFF_XK    44032    // f32[160] 640B
#define OFF_MASK  44672    // f32[32]  128B
#define OFF_SEL   44800    // u32[32]  128B
#define OFF_FEAT  44928    // f32[132] 528B
#define SMEM_TOTAL 45456

__global__ __launch_bounds__(TPB, 5)
void controller_kernel(
    const float4* __restrict__ states4,   // [N,4]
    const float*  __restrict__ goals,     // [N,2]
    const float*  __restrict__ W1,  const float* __restrict__ b1,
    const float*  __restrict__ W2,  const float* __restrict__ b2,
    const float*  __restrict__ Wd1, const float* __restrict__ bd1,
    const float*  __restrict__ Wd2, const float* __restrict__ bd2,
    const float*  __restrict__ Wd3, const float* __restrict__ bd3,
    const float*  __restrict__ Wd4, const float* __restrict__ bd4,
    float* __restrict__ out)              // [N,2]
{
    __shared__ __align__(16) char smem[SMEM_TOTAL];
    float*              w2t    = (float*)(smem + OFF_W2T);
    float*              h1s    = (float*)(smem + OFF_H1S);
    unsigned long long* skey   = (unsigned long long*)(smem + OFF_SKEY);
    float*              W1s    = (float*)(smem + OFF_W1S);
    float*              b1s    = (float*)(smem + OFF_B1S);
    float*              b2s    = (float*)(smem + OFF_B2S);
    float*              xkflat = (float*)(smem + OFF_XK);
    float*              masksh = (float*)(smem + OFF_MASK);
    unsigned*           selsh  = (unsigned*)(smem + OFF_SEL);
    float*              featsh = (float*)(smem + OFF_FEAT);
    float*              z1s    = (float*)(smem + OFF_Z1);
    float*              z2s    = (float*)(smem + OFF_Z2);
    float*              z3s    = (float*)(smem + OFF_Z3);
    float*              z4s    = (float*)(smem + OFF_Z4);

    const int tid  = threadIdx.x;
    const int i    = blockIdx.x;
    const int lane = tid & 31;
    const int wid  = tid >> 5;
    const float INF = __int_as_float(0x7f800000);

    const float4 si = states4[i];

    // ---- stage weights into shared ----
    for (int t = tid; t < 320; t += TPB) W1s[t] = W1[t];
    if (tid < 64)  b1s[tid] = b1[tid];
    if (tid < 128) b2s[tid] = b2[tid];
    for (int idx = tid; idx < 8192; idx += TPB) {
        int o = idx >> 6, c = idx & 63;          // coalesced global read
        w2t[c * W2T_LD + o] = W2[idx];
    }

    // ---- phase A: planar distances (d = sqrt, identical rounding to ref path) ----
    float dloc[JPT];
    {
        const float2* stxy = (const float2*)states4;
        #pragma unroll
        for (int k = 0; k < JPT; k++) {
            int j = tid + (k << 8);
            float2 sj = stxy[2 * j];
            float dx = si.x - sj.x;
            float dy = si.y - sj.y;
            dloc[k] = sqrtf(dx * dx + dy * dy + 1e-4f);
        }
    }

    // ---- phase B stage 1: per-warp exact top-32 of its 512, barrier-free ----
    // warp w owns j with (j & 255) in [32w, 32w+32)
    float my_d = 0.0f;   // lane r ends up holding the warp's rank-r element
    int   my_j = 0;
    {
        unsigned removed = 0;
        float lm_d = dloc[0]; int lm_k = 0;
        #pragma unroll
        for (int k = 1; k < JPT; k++)
            if (dloc[k] < lm_d) { lm_d = dloc[k]; lm_k = k; }
        int lm_j = tid + (lm_k << 8);

        #pragma unroll
        for (int r = 0; r < TOPK; r++) {
            float gd = lm_d;
            #pragma unroll
            for (int off = 16; off; off >>= 1)
                gd = fminf(gd, __shfl_xor_sync(0xffffffffu, gd, off));
            unsigned mm = __ballot_sync(0xffffffffu, lm_d == gd);
            int cj;
            if (__popc(mm) == 1) {                     // common: unique min-d lane
                cj = __shfl_sync(0xffffffffu, lm_j, __ffs(mm) - 1);
            } else {                                   // rare exact-d tie: min j
                int c = (lm_d == gd) ? lm_j : 0x7fffffff;
                #pragma unroll
                for (int off = 16; off; off >>= 1)
                    c = min(c, __shfl_xor_sync(0xffffffffu, c, off));
                cj = c;
            }
            if (lane == r) { my_d = gd; my_j = cj; }
            if (lm_j == cj) {                          // this lane's key won: remove + rescan
                removed |= (1u << lm_k);
                lm_d = INF; lm_k = 0;
                #pragma unroll
                for (int k = 0; k < JPT; k++) {
                    float dk = ((removed >> k) & 1u) ? INF : dloc[k];
                    if (dk < lm_d) { lm_d = dk; lm_k = k; }
                }
                lm_j = tid + (lm_k << 8);
            }
        }
        // publish sorted warp list as u64 keys (d_bits<<32 | j)
        skey[wid * 32 + lane] =
            (((unsigned long long)__float_as_uint(my_d)) << 32) | (unsigned)my_j;
    }
    __syncthreads();

    // ---- phase B stage 2: merge 8 sorted lists by exact rank ----
    {
        unsigned long long k64 = skey[tid];
        int rank = lane;                               // position in own sorted list
        #pragma unroll
        for (int ww = 0; ww < 8; ww++) {
            if (ww == wid) continue;
            const unsigned long long* arr = skey + ww * 32;
            int pos = 0;
            #pragma unroll
            for (int s = 16; s; s >>= 1)
                pos += (arr[pos + s - 1] < k64) ? s : 0;   // count strictly-less
            rank += pos;
        }
        if (rank < TOPK) selsh[rank] = (unsigned)(k64 & 0xffffffffu);
    }
    __syncthreads();

    // ---- gather xk rows + obs mask + tail features ----
    if (tid < TOPK) {
        int j = (int)selsh[tid];
        float4 sj = states4[j];
        float dx = si.x - sj.x;
        float dy = si.y - sj.y;
        xkflat[tid * 5 + 0] = dx;
        xkflat[tid * 5 + 1] = dy;
        xkflat[tid * 5 + 2] = si.z - sj.z;
        xkflat[tid * 5 + 3] = si.w - sj.w;
        xkflat[tid * 5 + 4] = (j == i) ? 1.0f : 0.0f;
        masksh[tid] = (sqrtf(dx * dx + dy * dy) < 1.0f) ? 1.0f : 0.0f;
    }
    if (tid == 0) {
        float gx = goals[2 * i], gy = goals[2 * i + 1];
        featsh[128] = si.x - gx;
        featsh[129] = si.y - gy;
        featsh[130] = si.z;
        featsh[131] = si.w;
    }
    __syncthreads();

    // ---- conv1 5->64 (raw-reshape view: h[c][p] = xkflat[c*32+p]) ----
    for (int idx = tid; idx < 2048; idx += TPB) {
        int o = idx >> 5, p = idx & 31;
        float acc = b1s[o];
        #pragma unroll
        for (int c = 0; c < 5; c++)
            acc = fmaf(W1s[o * 5 + c], xkflat[c * 32 + p], acc);
        h1s[idx] = fmaxf(acc, 0.0f);
    }
    __syncthreads();

    // ---- conv2 64->128 + masked argmax (4o x 4p register tile) ----
    {
        const int to = tid >> 3;           // o base = to*4   (0..31)
        const int tp = (tid & 7) << 2;     // p base          (0..28)
        float acc[4][4];
        #pragma unroll
        for (int oo = 0; oo < 4; oo++)
            #pragma unroll
            for (int pp = 0; pp < 4; pp++) acc[oo][pp] = 0.0f;

        #pragma unroll 2
        for (int c = 0; c < 64; c++) {
            const float4 w = *reinterpret_cast<const float4*>(&w2t[c * W2T_LD + (to << 2)]);
            const float4 h = *reinterpret_cast<const float4*>(&h1s[(c << 5) + tp]);
            const float ww[4] = {w.x, w.y, w.z, w.w};
            const float hh[4] = {h.x, h.y, h.z, h.w};
            #pragma unroll
            for (int oo = 0; oo < 4; oo++)
                #pragma unroll
                for (int pp = 0; pp < 4; pp++)
                    acc[oo][pp] = fmaf(ww[oo], hh[pp], acc[oo][pp]);
        }

        float mk[4];
        #pragma unroll
        for (int pp = 0; pp < 4; pp++) mk[pp] = masksh[tp + pp];

        #pragma unroll
        for (int oo = 0; oo < 4; oo++) {
            int o = (to << 2) + oo;
            float bb = b2s[o];
            float bv = 0.0f;
            int   bp = 0;
            #pragma unroll
            for (int pp = 0; pp < 4; pp++) {
                float v = fmaxf(acc[oo][pp] + bb, 0.0f) * mk[pp];
                if (pp == 0) { bv = v; bp = tp; }
                else if (v > bv) { bv = v; bp = tp + pp; }   // strict > keeps first index
            }
            #pragma unroll
            for (int off = 1; off < 8; off <<= 1) {
                float ov = __shfl_xor_sync(0xffffffffu, bv, off);
                int   op = __shfl_xor_sync(0xffffffffu, bp, off);
                if (ov > bv || (ov == bv && op < bp)) { bv = ov; bp = op; }
            }
            if ((tid & 7) == 0) featsh[o] = (float)bp;
        }
    }
    __syncthreads();

    // ---- MLP 132 -> 64 -> 128 -> 64 -> 4 ----
    for (int o = wid; o < 64; o += 8) {
        const float* wrow = Wd1 + o * 132;
        float s = fmaf(wrow[lane], featsh[lane], 0.0f);
        s = fmaf(wrow[lane + 32], featsh[lane + 32], s);
        s = fmaf(wrow[lane + 64], featsh[lane + 64], s);
        s = fmaf(wrow[lane + 96], featsh[lane + 96], s);
        if (lane < 4) s = fmaf(wrow[lane + 128], featsh[lane + 128], s);
        #pragma unroll
        for (int off = 16; off; off >>= 1) s += __shfl_xor_sync(0xffffffffu, s, off);
        if (lane == 0) z1s[o] = fmaxf(s + bd1[o], 0.0f);
    }
    __syncthreads();

    for (int o = wid; o < 128; o += 8) {
        float s = 0.0f;
        #pragma unroll
        for (int c = lane; c < 64; c += 32)
            s = fmaf(Wd2[o * 64 + c], z1s[c], s);
        #pragma unroll
        for (int off = 16; off; off >>= 1) s += __shfl_xor_sync(0xffffffffu, s, off);
        if (lane == 0) z2s[o] = fmaxf(s + bd2[o], 0.0f);
    }
    __syncthreads();

    for (int o = wid; o < 64; o += 8) {
        float s = 0.0f;
        #pragma unroll
        for (int c = lane; c < 128; c += 32)
            s = fmaf(Wd3[o * 128 + c], z2s[c], s);
        #pragma unroll
        for (int off = 16; off; off >>= 1) s += __shfl_xor_sync(0xffffffffu, s, off);
        if (lane == 0) z3s[o] = fmaxf(s + bd3[o], 0.0f);
    }
    __syncthreads();

    if (wid < 4) {
        int o = wid;
        float s = 0.0f;
        #pragma unroll
        for (int c = lane; c < 64; c += 32)
            s = fmaf(Wd4[o * 64 + c], z3s[c], s);
        #pragma unroll
        for (int off = 16; off; off >>= 1) s += __shfl_xor_sync(0xffffffffu, s, off);
        if (lane == 0) z4s[o] = s + bd4[o];
    }
    __syncthreads();

    // ---- gains + control output ----
    if (tid == 0) {
        float k0 = 2.0f / (1.0f + expf(-z4s[0])) + 0.2f;
        float k1 = 2.0f / (1.0f + expf(-z4s[1])) + 0.2f;
        float k2 = 2.0f / (1.0f + expf(-z4s[2])) + 0.2f;
        float k3 = 2.0f / (1.0f + expf(-z4s[3])) + 0.2f;
        float rx = featsh[128], ry = featsh[129];
        float v2 = featsh[130], v3 = featsh[131];
        out[2 * i + 0] = -(k0 * rx + k1 * v2);
        out[2 * i + 1] = -(k2 * ry + k3 * v3);
    }
}

extern "C" void kernel_launch(void* const* d_in, const int* in_sizes, int n_in,
                              void* d_out, int out_size)
{
    (void)in_sizes; (void)n_in; (void)out_size;
    controller_kernel<<<N_AGENTS, TPB>>>(
        (const float4*)d_in[0],  (const float*)d_in[1],
        (const float*)d_in[2],   (const float*)d_in[3],
        (const float*)d_in[4],   (const float*)d_in[5],
        (const float*)d_in[6],   (const float*)d_in[7],
        (const float*)d_in[8],   (const float*)d_in[9],
        (const float*)d_in[10],  (const float*)d_in[11],
        (const float*)d_in[12],  (const float*)d_in[13],
        (float*)d_out);
}

// round 6
// speedup vs baseline: 2.6190x; 1.3630x over previous
#include <cuda_runtime.h>

#define N_AGENTS 4096
#define TPB 256
#define JPT 16          // 4096/256 candidates per thread
#define TOPK 32
#define W2T_LD 132

// ---- static smem layout (byte offsets), phase-disjoint aliases ----
#define OFF_W2T   0        // f32[64*132] 33792B  (conv2)
                           //   alias: sorted keys u32[16][256] 16384B (selection)
#define OFF_Z1    0        //   alias: f32[64]  (post-conv2)
#define OFF_Z2    256      //   alias: f32[128]
#define OFF_Z3    768      //   alias: f32[64]
#define OFF_Z4    1024     //   alias: f32[4]
#define OFF_H1S   33792    // f32[64*32] 8192B (conv phases)
#define OFF_SKEY  33792    //   alias: u64[256] 2048B (merge, pre-conv1)
#define OFF_W1S   41984    // f32[320] 1280B
#define OFF_B1S   43264    // f32[64]  256B
#define OFF_B2S   43520    // f32[128] 512B
#define OFF_XK    44032    // f32[160] 640B
#define OFF_MASK  44672    // f32[32]  128B
#define OFF_SEL   44800    // u32[32]  128B
#define OFF_FEAT  44928    // f32[132] 528B
#define SMEM_TOTAL 45456

#define KEY_BIAS 0x3C000000u

__global__ __launch_bounds__(TPB, 5)
void controller_kernel(
    const float4* __restrict__ states4,   // [N,4]
    const float*  __restrict__ goals,     // [N,2]
    const float*  __restrict__ W1,  const float* __restrict__ b1,
    const float*  __restrict__ W2,  const float* __restrict__ b2,
    const float*  __restrict__ Wd1, const float* __restrict__ bd1,
    const float*  __restrict__ Wd2, const float* __restrict__ bd2,
    const float*  __restrict__ Wd3, const float* __restrict__ bd3,
    const float*  __restrict__ Wd4, const float* __restrict__ bd4,
    float* __restrict__ out)              // [N,2]
{
    __shared__ __align__(16) char smem[SMEM_TOTAL];
    float*              w2t     = (float*)(smem + OFF_W2T);
    unsigned*           sortbuf = (unsigned*)(smem + OFF_W2T);     // alias
    float*              h1s     = (float*)(smem + OFF_H1S);
    unsigned long long* skey    = (unsigned long long*)(smem + OFF_SKEY);
    float*              W1s     = (float*)(smem + OFF_W1S);
    float*              b1s     = (float*)(smem + OFF_B1S);
    float*              b2s     = (float*)(smem + OFF_B2S);
    float*              xkflat  = (float*)(smem + OFF_XK);
    float*              masksh  = (float*)(smem + OFF_MASK);
    unsigned*           selsh   = (unsigned*)(smem + OFF_SEL);
    float*              featsh  = (float*)(smem + OFF_FEAT);
    float*              z1s     = (float*)(smem + OFF_Z1);
    float*              z2s     = (float*)(smem + OFF_Z2);
    float*              z3s     = (float*)(smem + OFF_Z3);
    float*              z4s     = (float*)(smem + OFF_Z4);

    const int tid  = threadIdx.x;
    const int i    = blockIdx.x;
    const int lane = tid & 31;
    const int wid  = tid >> 5;

    const float4 si = states4[i];

    // ---- phase A: planar distances -> exact u32 keys (monotone in (d, k)) ----
    unsigned key[JPT];
    {
        const float2* stxy = (const float2*)states4;
        #pragma unroll
        for (int k = 0; k < JPT; k++) {
            int j = tid + (k << 8);
            float2 sj = stxy[2 * j];
            float dx = si.x - sj.x;
            float dy = si.y - sj.y;
            float d  = sqrtf(dx * dx + dy * dy + 1e-4f);   // identical to ref path
            key[k] = ((__float_as_uint(d) - KEY_BIAS) << 4) | (unsigned)k;
        }
    }

    // ---- per-thread Batcher odd-even mergesort of 16 keys (registers, 63 CEs) ----
    #pragma unroll
    for (int p = 1; p < 16; p <<= 1) {
        #pragma unroll
        for (int q = p; q > 0; q >>= 1) {
            #pragma unroll
            for (int jj = (q & (p - 1)); jj + q < 16; jj += (q << 1)) {
                #pragma unroll
                for (int ii = 0; ii < q; ii++) {
                    if (ii + jj + q < 16 &&
                        ((ii + jj) / (p << 1) == (ii + jj + q) / (p << 1))) {
                        unsigned a = key[ii + jj], b = key[ii + jj + q];
                        key[ii + jj]     = umin(a, b);
                        key[ii + jj + q] = umax(a, b);
                    }
                }
            }
        }
    }
    // spill sorted column to smem (own column only -> warp-sync safe, no barrier)
    #pragma unroll
    for (int k = 0; k < 16; k++) sortbuf[(k << 8) + tid] = key[k];

    // ---- stage 1: per-warp exact top-32, rescan-free tournament ----
    unsigned winkey = 0;
    int      winlane = 0;
    {
        unsigned cur = key[0];
        int head = 1;
        #pragma unroll
        for (int r = 0; r < TOPK; r++) {
            unsigned g = cur;
            g = umin(g, __shfl_xor_sync(0xffffffffu, g, 16));
            g = umin(g, __shfl_xor_sync(0xffffffffu, g, 8));
            g = umin(g, __shfl_xor_sync(0xffffffffu, g, 4));
            g = umin(g, __shfl_xor_sync(0xffffffffu, g, 2));
            g = umin(g, __shfl_xor_sync(0xffffffffu, g, 1));
            unsigned mm = __ballot_sync(0xffffffffu, cur == g);
            int l = __ffs(mm) - 1;          // lowest lane = lowest j on key ties
            if (lane == r) { winkey = g; winlane = l; }
            if (lane == l) {                // winner pops next from its sorted list
                cur = (head < 16) ? sortbuf[(head << 8) + tid] : 0xffffffffu;
                head++;
            }
        }
    }
    // publish rank-`lane` winner as global u64 key (d_bits<<32 | j)
    {
        unsigned dbits = (winkey >> 4) + KEY_BIAS;
        unsigned j = (unsigned)((wid << 5) + winlane) + ((winkey & 15u) << 8);
        skey[tid] = (((unsigned long long)dbits) << 32) | j;
    }
    __syncthreads();

    // ---- merge phase: stage weights (overlaps LDS chains) + rank-merge ----
    for (int t = tid; t < 320; t += TPB) W1s[t] = W1[t];
    if (tid < 64)  b1s[tid] = b1[tid];
    if (tid < 128) b2s[tid] = b2[tid];
    for (int idx = tid; idx < 8192; idx += TPB) {
        int o = idx >> 6, c = idx & 63;          // coalesced global read
        w2t[c * W2T_LD + o] = W2[idx];
    }
    {
        unsigned long long k64 = skey[tid];
        int rank = lane;                         // position in own sorted list
        #pragma unroll
        for (int ww = 0; ww < 8; ww++) {
            if (ww == wid) continue;
            const unsigned long long* arr = skey + ww * 32;
            int pos = 0;
            #pragma unroll
            for (int s = 16; s; s >>= 1)
                pos += (arr[pos + s - 1] < k64) ? s : 0;   // count strictly-less
            rank += pos;
        }
        if (rank < TOPK) selsh[rank] = (unsigned)(k64 & 0xffffffffu);
    }
    __syncthreads();

    // ---- gather xk rows + obs mask + tail features ----
    if (tid < TOPK) {
        int j = (int)selsh[tid];
        float4 sj = states4[j];
        float dx = si.x - sj.x;
        float dy = si.y - sj.y;
        xkflat[tid * 5 + 0] = dx;
        xkflat[tid * 5 + 1] = dy;
        xkflat[tid * 5 + 2] = si.z - sj.z;
        xkflat[tid * 5 + 3] = si.w - sj.w;
        xkflat[tid * 5 + 4] = (j == i) ? 1.0f : 0.0f;
        masksh[tid] = (sqrtf(dx * dx + dy * dy) < 1.0f) ? 1.0f : 0.0f;
    }
    if (tid == 0) {
        float gx = goals[2 * i], gy = goals[2 * i + 1];
        featsh[128] = si.x - gx;
        featsh[129] = si.y - gy;
        featsh[130] = si.z;
        featsh[131] = si.w;
    }
    __syncthreads();

    // ---- conv1 5->64 (raw-reshape view: h[c][p] = xkflat[c*32+p]) ----
    for (int idx = tid; idx < 2048; idx += TPB) {
        int o = idx >> 5, p = idx & 31;
        float acc = b1s[o];
        #pragma unroll
        for (int c = 0; c < 5; c++)
            acc = fmaf(W1s[o * 5 + c], xkflat[c * 32 + p], acc);
        h1s[idx] = fmaxf(acc, 0.0f);
    }
    __syncthreads();

    // ---- conv2 64->128 + masked argmax (4o x 4p register tile) ----
    {
        const int to = tid >> 3;           // o base = to*4   (0..31)
        const int tp = (tid & 7) << 2;     // p base          (0..28)
        float acc[4][4];
        #pragma unroll
        for (int oo = 0; oo < 4; oo++)
            #pragma unroll
            for (int pp = 0; pp < 4; pp++) acc[oo][pp] = 0.0f;

        #pragma unroll 2
        for (int c = 0; c < 64; c++) {
            const float4 w = *reinterpret_cast<const float4*>(&w2t[c * W2T_LD + (to << 2)]);
            const float4 h = *reinterpret_cast<const float4*>(&h1s[(c << 5) + tp]);
            const float ww[4] = {w.x, w.y, w.z, w.w};
            const float hh[4] = {h.x, h.y, h.z, h.w};
            #pragma unroll
            for (int oo = 0; oo < 4; oo++)
                #pragma unroll
                for (int pp = 0; pp < 4; pp++)
                    acc[oo][pp] = fmaf(ww[oo], hh[pp], acc[oo][pp]);
        }

        float mk[4];
        #pragma unroll
        for (int pp = 0; pp < 4; pp++) mk[pp] = masksh[tp + pp];

        #pragma unroll
        for (int oo = 0; oo < 4; oo++) {
            int o = (to << 2) + oo;
            float bb = b2s[o];
            float bv = 0.0f;
            int   bp = 0;
            #pragma unroll
            for (int pp = 0; pp < 4; pp++) {
                float v = fmaxf(acc[oo][pp] + bb, 0.0f) * mk[pp];
                if (pp == 0) { bv = v; bp = tp; }
                else if (v > bv) { bv = v; bp = tp + pp; }   // strict > keeps first index
            }
            #pragma unroll
            for (int off = 1; off < 8; off <<= 1) {
                float ov = __shfl_xor_sync(0xffffffffu, bv, off);
                int   op = __shfl_xor_sync(0xffffffffu, bp, off);
                if (ov > bv || (ov == bv && op < bp)) { bv = ov; bp = op; }
            }
            if ((tid & 7) == 0) featsh[o] = (float)bp;
        }
    }
    __syncthreads();

    // ---- MLP 132 -> 64 -> 128 -> 64 -> 4 ----
    for (int o = wid; o < 64; o += 8) {
        const float* wrow = Wd1 + o * 132;
        float s = fmaf(wrow[lane], featsh[lane], 0.0f);
        s = fmaf(wrow[lane + 32], featsh[lane + 32], s);
        s = fmaf(wrow[lane + 64], featsh[lane + 64], s);
        s = fmaf(wrow[lane + 96], featsh[lane + 96], s);
        if (lane < 4) s = fmaf(wrow[lane + 128], featsh[lane + 128], s);
        #pragma unroll
        for (int off = 16; off; off >>= 1) s += __shfl_xor_sync(0xffffffffu, s, off);
        if (lane == 0) z1s[o] = fmaxf(s + bd1[o], 0.0f);
    }
    __syncthreads();

    for (int o = wid; o < 128; o += 8) {
        float s = 0.0f;
        #pragma unroll
        for (int c = lane; c < 64; c += 32)
            s = fmaf(Wd2[o * 64 + c], z1s[c], s);
        #pragma unroll
        for (int off = 16; off; off >>= 1) s += __shfl_xor_sync(0xffffffffu, s, off);
        if (lane == 0) z2s[o] = fmaxf(s + bd2[o], 0.0f);
    }
    __syncthreads();

    for (int o = wid; o < 64; o += 8) {
        float s = 0.0f;
        #pragma unroll
        for (int c = lane; c < 128; c += 32)
            s = fmaf(Wd3[o * 128 + c], z2s[c], s);
        #pragma unroll
        for (int off = 16; off; off >>= 1) s += __shfl_xor_sync(0xffffffffu, s, off);
        if (lane == 0) z3s[o] = fmaxf(s + bd3[o], 0.0f);
    }
    __syncthreads();

    if (wid < 4) {
        int o = wid;
        float s = 0.0f;
        #pragma unroll
        for (int c = lane; c < 64; c += 32)
            s = fmaf(Wd4[o * 64 + c], z3s[c], s);
        #pragma unroll
        for (int off = 16; off; off >>= 1) s += __shfl_xor_sync(0xffffffffu, s, off);
        if (lane == 0) z4s[o] = s + bd4[o];
    }
    __syncthreads();

    // ---- gains + control output ----
    if (tid == 0) {
        float k0 = 2.0f / (1.0f + expf(-z4s[0])) + 0.2f;
        float k1 = 2.0f / (1.0f + expf(-z4s[1])) + 0.2f;
        float k2 = 2.0f / (1.0f + expf(-z4s[2])) + 0.2f;
        float k3 = 2.0f / (1.0f + expf(-z4s[3])) + 0.2f;
        float rx = featsh[128], ry = featsh[129];
        float v2 = featsh[130], v3 = featsh[131];
        out[2 * i + 0] = -(k0 * rx + k1 * v2);
        out[2 * i + 1] = -(k2 * ry + k3 * v3);
    }
}

extern "C" void kernel_launch(void* const* d_in, const int* in_sizes, int n_in,
                              void* d_out, int out_size)
{
    (void)in_sizes; (void)n_in; (void)out_size;
    controller_kernel<<<N_AGENTS, TPB>>>(
        (const float4*)d_in[0],  (const float*)d_in[1],
        (const float*)d_in[2],   (const float*)d_in[3],
        (const float*)d_in[4],   (const float*)d_in[5],
        (const float*)d_in[6],   (const float*)d_in[7],
        (const float*)d_in[8],   (const float*)d_in[9],
        (const float*)d_in[10],  (const float*)d_in[11],
        (const float*)d_in[12],  (const float*)d_in[13],
        (float*)d_out);
}

// round 7
// speedup vs baseline: 3.7555x; 1.4340x over previous
#include <cuda_runtime.h>

#define N_AGENTS 4096
#define TPB 256
#define JPT 16          // 4096/256 candidates per thread
#define TOPK 32
#define W2T_LD 132

// ---- static smem layout (byte offsets), phase-disjoint aliases ----
#define OFF_W2T   0        // f32[64*132] 33792B  (conv2)
                           //   alias: sorted keys u32[16][256] 16384B (selection)
#define OFF_Z1    0        //   alias: f32[64]  (post-conv2)
#define OFF_Z2    256      //   alias: f32[128]
#define OFF_Z3    768      //   alias: f32[64]
#define OFF_Z4    1024     //   alias: f32[4]
#define OFF_H1S   33792    // f32[64*32] 8192B (conv phases)
#define OFF_SKEY  33792    //   alias: u64[256] 2048B (merge, pre-conv1)
#define OFF_W1S   41984    // f32[320] 1280B
#define OFF_B1S   43264    // f32[64]  256B
#define OFF_B2S   43520    // f32[128] 512B
#define OFF_XK    44032    // f32[160] 640B
#define OFF_MASK  44672    // f32[32]  128B
#define OFF_SEL   44800    // u32[32]  128B
#define OFF_FEAT  44928    // f32[132] 528B
#define SMEM_TOTAL 45456

#define KEY_BIAS 0x3C000000u

__global__ __launch_bounds__(TPB, 5)
void controller_kernel(
    const float4* __restrict__ states4,   // [N,4]
    const float*  __restrict__ goals,     // [N,2]
    const float*  __restrict__ W1,  const float* __restrict__ b1,
    const float*  __restrict__ W2,  const float* __restrict__ b2,
    const float*  __restrict__ Wd1, const float* __restrict__ bd1,
    const float*  __restrict__ Wd2, const float* __restrict__ bd2,
    const float*  __restrict__ Wd3, const float* __restrict__ bd3,
    const float*  __restrict__ Wd4, const float* __restrict__ bd4,
    float* __restrict__ out)              // [N,2]
{
    __shared__ __align__(16) char smem[SMEM_TOTAL];
    float*              w2t     = (float*)(smem + OFF_W2T);
    unsigned*           sortbuf = (unsigned*)(smem + OFF_W2T);     // alias
    float*              h1s     = (float*)(smem + OFF_H1S);
    unsigned long long* skey    = (unsigned long long*)(smem + OFF_SKEY);
    float*              W1s     = (float*)(smem + OFF_W1S);
    float*              b1s     = (float*)(smem + OFF_B1S);
    float*              b2s     = (float*)(smem + OFF_B2S);
    float*              xkflat  = (float*)(smem + OFF_XK);
    float*              masksh  = (float*)(smem + OFF_MASK);
    unsigned*           selsh   = (unsigned*)(smem + OFF_SEL);
    float*              featsh  = (float*)(smem + OFF_FEAT);
    float*              z1s     = (float*)(smem + OFF_Z1);
    float*              z2s     = (float*)(smem + OFF_Z2);
    float*              z3s     = (float*)(smem + OFF_Z3);
    float*              z4s     = (float*)(smem + OFF_Z4);

    const int tid  = threadIdx.x;
    const int i    = blockIdx.x;
    const int lane = tid & 31;
    const int wid  = tid >> 5;

    const float4 si = states4[i];

    // ---- phase A: planar distances -> exact u32 keys (monotone in (d, k)) ----
    unsigned key[JPT];
    {
        const float2* stxy = (const float2*)states4;
        #pragma unroll
        for (int k = 0; k < JPT; k++) {
            int j = tid + (k << 8);
            float2 sj = stxy[2 * j];
            float dx = si.x - sj.x;
            float dy = si.y - sj.y;
            float d  = sqrtf(dx * dx + dy * dy + 1e-4f);   // identical to ref path
            key[k] = ((__float_as_uint(d) - KEY_BIAS) << 4) | (unsigned)k;
        }
    }

    // ---- per-thread Batcher odd-even mergesort of 16 keys (registers, 63 CEs) ----
    #pragma unroll
    for (int p = 1; p < 16; p <<= 1) {
        #pragma unroll
        for (int q = p; q > 0; q >>= 1) {
            #pragma unroll
            for (int jj = (q & (p - 1)); jj + q < 16; jj += (q << 1)) {
                #pragma unroll
                for (int ii = 0; ii < q; ii++) {
                    if (ii + jj + q < 16 &&
                        ((ii + jj) / (p << 1) == (ii + jj + q) / (p << 1))) {
                        unsigned a = key[ii + jj], b = key[ii + jj + q];
                        key[ii + jj]     = umin(a, b);
                        key[ii + jj + q] = umax(a, b);
                    }
                }
            }
        }
    }
    // spill sorted column to smem (own column only -> warp-sync safe, no barrier)
    #pragma unroll
    for (int k = 0; k < 16; k++) sortbuf[(k << 8) + tid] = key[k];

    // ---- stage 1: per-warp exact top-32, REDUX tournament ----
    unsigned winkey = 0;
    int      winlane = 0;
    {
        unsigned cur = key[0];
        int head = 1;
        #pragma unroll
        for (int r = 0; r < TOPK; r++) {
            unsigned g = __reduce_min_sync(0xffffffffu, cur);
            unsigned mm = __ballot_sync(0xffffffffu, cur == g);
            int l = __ffs(mm) - 1;          // lowest lane = lowest j on key ties
            if (lane == r) { winkey = g; winlane = l; }
            if (lane == l) {                // winner pops next from its sorted list
                cur = (head < 16) ? sortbuf[(head << 8) + tid] : 0xffffffffu;
                head++;
            }
        }
    }
    // publish rank-`lane` winner as global u64 key (d_bits<<32 | j)
    {
        unsigned dbits = (winkey >> 4) + KEY_BIAS;
        unsigned j = (unsigned)((wid << 5) + winlane) + ((winkey & 15u) << 8);
        skey[tid] = (((unsigned long long)dbits) << 32) | j;
    }
    __syncthreads();

    // ---- merge phase: stage weights (overlaps LDS chains) + rank-merge ----
    for (int t = tid; t < 320; t += TPB) W1s[t] = W1[t];
    if (tid < 64)  b1s[tid] = b1[tid];
    if (tid < 128) b2s[tid] = b2[tid];
    for (int idx = tid; idx < 8192; idx += TPB) {
        int o = idx >> 6, c = idx & 63;          // coalesced global read
        w2t[c * W2T_LD + o] = W2[idx];
    }
    {
        unsigned long long k64 = skey[tid];
        int rank = lane;                         // position in own sorted list
        #pragma unroll
        for (int ww = 0; ww < 8; ww++) {
            if (ww == wid) continue;
            const unsigned long long* arr = skey + ww * 32;
            int pos = 0;
            #pragma unroll
            for (int s = 16; s; s >>= 1)
                pos += (arr[pos + s - 1] < k64) ? s : 0;   // count strictly-less
            rank += pos;
        }
        if (rank < TOPK) selsh[rank] = (unsigned)(k64 & 0xffffffffu);
    }
    __syncthreads();

    // ---- gather xk rows + obs mask + tail features ----
    if (tid < TOPK) {
        int j = (int)selsh[tid];
        float4 sj = states4[j];
        float dx = si.x - sj.x;
        float dy = si.y - sj.y;
        xkflat[tid * 5 + 0] = dx;
        xkflat[tid * 5 + 1] = dy;
        xkflat[tid * 5 + 2] = si.z - sj.z;
        xkflat[tid * 5 + 3] = si.w - sj.w;
        xkflat[tid * 5 + 4] = (j == i) ? 1.0f : 0.0f;
        masksh[tid] = (sqrtf(dx * dx + dy * dy) < 1.0f) ? 1.0f : 0.0f;
    }
    if (tid == 0) {
        float gx = goals[2 * i], gy = goals[2 * i + 1];
        featsh[128] = si.x - gx;
        featsh[129] = si.y - gy;
        featsh[130] = si.z;
        featsh[131] = si.w;
    }
    __syncthreads();

    // ---- conv1 5->64 (raw-reshape view: h[c][p] = xkflat[c*32+p]) ----
    for (int idx = tid; idx < 2048; idx += TPB) {
        int o = idx >> 5, p = idx & 31;
        float acc = b1s[o];
        #pragma unroll
        for (int c = 0; c < 5; c++)
            acc = fmaf(W1s[o * 5 + c], xkflat[c * 32 + p], acc);
        h1s[idx] = fmaxf(acc, 0.0f);
    }
    __syncthreads();

    // ---- conv2 64->128 + masked argmax: f32x2 packed over p-pairs ----
    {
        const int to = tid >> 3;           // o base = to*4   (0..31)
        const int tp = (tid & 7) << 2;     // p base          (0..28)
        unsigned long long accp[4][2];     // [oo][p-pair], f32x2 accumulators
        #pragma unroll
        for (int oo = 0; oo < 4; oo++) { accp[oo][0] = 0ull; accp[oo][1] = 0ull; }

        #pragma unroll 2
        for (int c = 0; c < 64; c++) {
            const float4 w = *reinterpret_cast<const float4*>(&w2t[c * W2T_LD + (to << 2)]);
            const ulonglong2 hv = *reinterpret_cast<const ulonglong2*>(&h1s[(c << 5) + tp]);
            // duplicate each w into a {w,w} pair
            unsigned long long wd[4];
            asm("mov.b64 %0, {%1, %1};" : "=l"(wd[0]) : "f"(w.x));
            asm("mov.b64 %0, {%1, %1};" : "=l"(wd[1]) : "f"(w.y));
            asm("mov.b64 %0, {%1, %1};" : "=l"(wd[2]) : "f"(w.z));
            asm("mov.b64 %0, {%1, %1};" : "=l"(wd[3]) : "f"(w.w));
            #pragma unroll
            for (int oo = 0; oo < 4; oo++) {
                asm("fma.rn.f32x2 %0, %1, %2, %0;" : "+l"(accp[oo][0]) : "l"(wd[oo]), "l"(hv.x));
                asm("fma.rn.f32x2 %0, %1, %2, %0;" : "+l"(accp[oo][1]) : "l"(wd[oo]), "l"(hv.y));
            }
        }

        float acc[4][4];
        #pragma unroll
        for (int oo = 0; oo < 4; oo++) {
            asm("mov.b64 {%0, %1}, %2;" : "=f"(acc[oo][0]), "=f"(acc[oo][1]) : "l"(accp[oo][0]));
            asm("mov.b64 {%0, %1}, %2;" : "=f"(acc[oo][2]), "=f"(acc[oo][3]) : "l"(accp[oo][1]));
        }

        float mk[4];
        #pragma unroll
        for (int pp = 0; pp < 4; pp++) mk[pp] = masksh[tp + pp];

        #pragma unroll
        for (int oo = 0; oo < 4; oo++) {
            int o = (to << 2) + oo;
            float bb = b2s[o];
            float bv = 0.0f;
            int   bp = 0;
            #pragma unroll
            for (int pp = 0; pp < 4; pp++) {
                float v = fmaxf(acc[oo][pp] + bb, 0.0f) * mk[pp];
                if (pp == 0) { bv = v; bp = tp; }
                else if (v > bv) { bv = v; bp = tp + pp; }   // strict > keeps first index
            }
            #pragma unroll
            for (int off = 1; off < 8; off <<= 1) {
                float ov = __shfl_xor_sync(0xffffffffu, bv, off);
                int   op = __shfl_xor_sync(0xffffffffu, bp, off);
                if (ov > bv || (ov == bv && op < bp)) { bv = ov; bp = op; }
            }
            if ((tid & 7) == 0) featsh[o] = (float)bp;
        }
    }
    __syncthreads();

    // ---- MLP 132 -> 64 -> 128 -> 64 -> 4 (half-warp float4 dots) ----
    const int hw = lane >> 4;        // half-warp id (0/1)
    const int hl = lane & 15;        // lane within half

    // z1: 64 outputs, 2 per warp per iter
    #pragma unroll
    for (int it = 0; it < 4; it++) {
        int o = (wid << 3) + (it << 1) + hw;
        const float4* wr = (const float4*)(Wd1 + o * 132);
        float4 wa = wr[hl];
        float4 fa = *(const float4*)&featsh[hl << 2];
        float s = wa.x * fa.x;
        s = fmaf(wa.y, fa.y, s); s = fmaf(wa.z, fa.z, s); s = fmaf(wa.w, fa.w, s);
        float4 wb = wr[hl + 16];
        float4 fb = *(const float4*)&featsh[64 + (hl << 2)];
        s = fmaf(wb.x, fb.x, s); s = fmaf(wb.y, fb.y, s);
        s = fmaf(wb.z, fb.z, s); s = fmaf(wb.w, fb.w, s);
        if (hl == 0) {
            float4 wc = wr[32];
            float4 fc = *(const float4*)&featsh[128];
            s = fmaf(wc.x, fc.x, s); s = fmaf(wc.y, fc.y, s);
            s = fmaf(wc.z, fc.z, s); s = fmaf(wc.w, fc.w, s);
        }
        #pragma unroll
        for (int off = 8; off; off >>= 1) s += __shfl_xor_sync(0xffffffffu, s, off);
        if (hl == 0) z1s[o] = fmaxf(s + bd1[o], 0.0f);
    }
    __syncthreads();

    // z2: 128 outputs, 2 per warp per iter
    #pragma unroll
    for (int it = 0; it < 8; it++) {
        int o = (wid << 4) + (it << 1) + hw;
        float4 w = ((const float4*)(Wd2 + (o << 6)))[hl];
        float4 z = ((const float4*)z1s)[hl];
        float s = w.x * z.x;
        s = fmaf(w.y, z.y, s); s = fmaf(w.z, z.z, s); s = fmaf(w.w, z.w, s);
        #pragma unroll
        for (int off = 8; off; off >>= 1) s += __shfl_xor_sync(0xffffffffu, s, off);
        if (hl == 0) z2s[o] = fmaxf(s + bd2[o], 0.0f);
    }
    __syncthreads();

    // z3: 64 outputs, 2 per warp per iter (128 inputs = two float4 passes)
    #pragma unroll
    for (int it = 0; it < 4; it++) {
        int o = (wid << 3) + (it << 1) + hw;
        const float4* wr = (const float4*)(Wd3 + (o << 7));
        float4 wa = wr[hl];
        float4 za = ((const float4*)z2s)[hl];
        float s = wa.x * za.x;
        s = fmaf(wa.y, za.y, s); s = fmaf(wa.z, za.z, s); s = fmaf(wa.w, za.w, s);
        float4 wb = wr[hl + 16];
        float4 zb = ((const float4*)z2s)[hl + 16];
        s = fmaf(wb.x, zb.x, s); s = fmaf(wb.y, zb.y, s);
        s = fmaf(wb.z, zb.z, s); s = fmaf(wb.w, zb.w, s);
        #pragma unroll
        for (int off = 8; off; off >>= 1) s += __shfl_xor_sync(0xffffffffu, s, off);
        if (hl == 0) z3s[o] = fmaxf(s + bd3[o], 0.0f);
    }
    __syncthreads();

    // z4: 4 outputs on warps 0-1
    if (wid < 2) {
        int o = (wid << 1) + hw;
        float4 w = ((const float4*)(Wd4 + (o << 6)))[hl];
        float4 z = ((const float4*)z3s)[hl];
        float s = w.x * z.x;
        s = fmaf(w.y, z.y, s); s = fmaf(w.z, z.z, s); s = fmaf(w.w, z.w, s);
        #pragma unroll
        for (int off = 8; off; off >>= 1) s += __shfl_xor_sync(0xffffffffu, s, off);
        if (hl == 0) z4s[o] = s + bd4[o];
    }
    __syncthreads();

    // ---- gains + control output ----
    if (tid == 0) {
        float k0 = 2.0f / (1.0f + expf(-z4s[0])) + 0.2f;
        float k1 = 2.0f / (1.0f + expf(-z4s[1])) + 0.2f;
        float k2 = 2.0f / (1.0f + expf(-z4s[2])) + 0.2f;
        float k3 = 2.0f / (1.0f + expf(-z4s[3])) + 0.2f;
        float rx = featsh[128], ry = featsh[129];
        float v2 = featsh[130], v3 = featsh[131];
        out[2 * i + 0] = -(k0 * rx + k1 * v2);
        out[2 * i + 1] = -(k2 * ry + k3 * v3);
    }
}

extern "C" void kernel_launch(void* const* d_in, const int* in_sizes, int n_in,
                              void* d_out, int out_size)
{
    (void)in_sizes; (void)n_in; (void)out_size;
    controller_kernel<<<N_AGENTS, TPB>>>(
        (const float4*)d_in[0],  (const float*)d_in[1],
        (const float*)d_in[2],   (const float*)d_in[3],
        (const float*)d_in[4],   (const float*)d_in[5],
        (const float*)d_in[6],   (const float*)d_in[7],
        (const float*)d_in[8],   (const float*)d_in[9],
        (const float*)d_in[10],  (const float*)d_in[11],
        (const float*)d_in[12],  (const float*)d_in[13],
        (float*)d_out);
}

// round 8
// speedup vs baseline: 3.8108x; 1.0147x over previous
#include <cuda_runtime.h>

#define N_AGENTS 4096
#define TPB 256
#define JPT 16          // 4096/256 candidates per thread
#define TOPK 32
#define W2S_LD 68       // padded row: 68 ≡ 4 (mod 8) -> conflict-free o-adjacent float4 reads

// ---- static smem layout (byte offsets), phase-disjoint aliases ----
#define OFF_W2S   0        // f32[128*68] 34816B (conv2)
                           //   alias: sorted keys u32[16][256] 16384B (selection)
#define OFF_Z1    0        //   alias: f32[64]  (post-conv2)
#define OFF_Z2    256      //   alias: f32[128]
#define OFF_Z3    768      //   alias: f32[64]
#define OFF_Z4    1024     //   alias: f32[4]
#define OFF_H1S   34816    // f32[64*32] 8192B (conv phases)
#define OFF_SKEY  34816    //   alias: u64[256] 2048B (merge, pre-conv1)
#define OFF_W1S   43008    // f32[320] 1280B
#define OFF_B1S   44288    // f32[64]  256B
#define OFF_B2S   44544    // f32[128] 512B
#define OFF_XK    45056    // f32[160] 640B  (alias: featsh[0..127] post-conv1)
#define OFF_MASK  45696    // f32[32]  128B
#define OFF_SEL   45824    // u32[32]  128B
#define OFF_TAIL  45952    // f32[4]   16B   (rel.x, rel.y, v2, v3)
#define SMEM_TOTAL 45968

#define KEY_BIAS 0x3C000000u

__global__ __launch_bounds__(TPB, 5)
void controller_kernel(
    const float4* __restrict__ states4,   // [N,4]
    const float*  __restrict__ goals,     // [N,2]
    const float*  __restrict__ W1,  const float* __restrict__ b1,
    const float*  __restrict__ W2,  const float* __restrict__ b2,
    const float*  __restrict__ Wd1, const float* __restrict__ bd1,
    const float*  __restrict__ Wd2, const float* __restrict__ bd2,
    const float*  __restrict__ Wd3, const float* __restrict__ bd3,
    const float*  __restrict__ Wd4, const float* __restrict__ bd4,
    float* __restrict__ out)              // [N,2]
{
    __shared__ __align__(16) char smem[SMEM_TOTAL];
    float*              w2s     = (float*)(smem + OFF_W2S);
    float4*             w2s4    = (float4*)(smem + OFF_W2S);
    unsigned*           sortbuf = (unsigned*)(smem + OFF_W2S);    // alias (selection)
    float*              h1s     = (float*)(smem + OFF_H1S);
    unsigned long long* skey    = (unsigned long long*)(smem + OFF_SKEY);
    float*              W1s     = (float*)(smem + OFF_W1S);
    float*              b1s     = (float*)(smem + OFF_B1S);
    float*              b2s     = (float*)(smem + OFF_B2S);
    float*              xkflat  = (float*)(smem + OFF_XK);
    float*              featsh  = (float*)(smem + OFF_XK);        // alias (post-conv1)
    float*              masksh  = (float*)(smem + OFF_MASK);
    unsigned*           selsh   = (unsigned*)(smem + OFF_SEL);
    float*              tailf   = (float*)(smem + OFF_TAIL);
    float*              z1s     = (float*)(smem + OFF_Z1);
    float*              z2s     = (float*)(smem + OFF_Z2);
    float*              z3s     = (float*)(smem + OFF_Z3);
    float*              z4s     = (float*)(smem + OFF_Z4);

    const int tid  = threadIdx.x;
    const int i    = blockIdx.x;
    const int lane = tid & 31;
    const int wid  = tid >> 5;

    const float4 si = states4[i];

    // ---- phase A: planar distances -> exact u32 keys (monotone in (d, k)) ----
    unsigned key[JPT];
    {
        const float2* stxy = (const float2*)states4;
        #pragma unroll
        for (int k = 0; k < JPT; k++) {
            int j = tid + (k << 8);
            float2 sj = stxy[2 * j];
            float dx = si.x - sj.x;
            float dy = si.y - sj.y;
            float d  = sqrtf(dx * dx + dy * dy + 1e-4f);   // identical to ref path
            key[k] = ((__float_as_uint(d) - KEY_BIAS) << 4) | (unsigned)k;
        }
    }

    // ---- per-thread Batcher odd-even mergesort of 16 keys (registers, 63 CEs) ----
    #pragma unroll
    for (int p = 1; p < 16; p <<= 1) {
        #pragma unroll
        for (int q = p; q > 0; q >>= 1) {
            #pragma unroll
            for (int jj = (q & (p - 1)); jj + q < 16; jj += (q << 1)) {
                #pragma unroll
                for (int ii = 0; ii < q; ii++) {
                    if (ii + jj + q < 16 &&
                        ((ii + jj) / (p << 1) == (ii + jj + q) / (p << 1))) {
                        unsigned a = key[ii + jj], b = key[ii + jj + q];
                        key[ii + jj]     = umin(a, b);
                        key[ii + jj + q] = umax(a, b);
                    }
                }
            }
        }
    }
    // spill sorted column to smem (own column only -> warp-sync safe, no barrier)
    #pragma unroll
    for (int k = 0; k < 16; k++) sortbuf[(k << 8) + tid] = key[k];

    // ---- stage 1: per-warp exact top-32, REDUX tournament ----
    unsigned winkey = 0;
    int      winlane = 0;
    {
        unsigned cur = key[0];
        int head = 1;
        #pragma unroll
        for (int r = 0; r < TOPK; r++) {
            unsigned g = __reduce_min_sync(0xffffffffu, cur);
            unsigned mm = __ballot_sync(0xffffffffu, cur == g);
            int l = __ffs(mm) - 1;          // lowest lane = lowest j on key ties
            if (lane == r) { winkey = g; winlane = l; }
            if (lane == l) {                // winner pops next from its sorted list
                cur = (head < 16) ? sortbuf[(head << 8) + tid] : 0xffffffffu;
                head++;
            }
        }
    }
    // publish rank-`lane` winner as global u64 key (d_bits<<32 | j)
    {
        unsigned dbits = (winkey >> 4) + KEY_BIAS;
        unsigned j = (unsigned)((wid << 5) + winlane) + ((winkey & 15u) << 8);
        skey[tid] = (((unsigned long long)dbits) << 32) | j;
    }
    __syncthreads();

    // ---- merge phase: stage weights (overlaps LDS chains) + rank-merge ----
    for (int t = tid; t < 320; t += TPB) W1s[t] = W1[t];
    if (tid < 64)  b1s[tid] = b1[tid];
    if (tid < 128) b2s[tid] = b2[tid];
    {
        const float4* W2v = (const float4*)W2;     // [128][16] float4, identity copy
        #pragma unroll
        for (int t = tid; t < 2048; t += TPB) {
            int o = t >> 4, cb = t & 15;
            w2s4[o * (W2S_LD / 4) + cb] = W2v[t];  // row stride 17 float4 = 68 f32
        }
    }
    {
        unsigned long long k64 = skey[tid];
        int rank = lane;                           // position in own sorted list
        #pragma unroll
        for (int ww = 0; ww < 8; ww++) {
            if (ww == wid) continue;
            const unsigned long long* arr = skey + ww * 32;
            int pos = 0;
            #pragma unroll
            for (int s = 16; s; s >>= 1)
                pos += (arr[pos + s - 1] < k64) ? s : 0;   // count strictly-less
            rank += pos;
        }
        if (rank < TOPK) selsh[rank] = (unsigned)(k64 & 0xffffffffu);
    }
    __syncthreads();

    // ---- gather xk rows + obs mask + tail features ----
    if (tid < TOPK) {
        int j = (int)selsh[tid];
        float4 sj = states4[j];
        float dx = si.x - sj.x;
        float dy = si.y - sj.y;
        xkflat[tid * 5 + 0] = dx;
        xkflat[tid * 5 + 1] = dy;
        xkflat[tid * 5 + 2] = si.z - sj.z;
        xkflat[tid * 5 + 3] = si.w - sj.w;
        xkflat[tid * 5 + 4] = (j == i) ? 1.0f : 0.0f;
        masksh[tid] = (sqrtf(dx * dx + dy * dy) < 1.0f) ? 1.0f : 0.0f;
    }
    if (tid == 0) {
        float gx = goals[2 * i], gy = goals[2 * i + 1];
        tailf[0] = si.x - gx;
        tailf[1] = si.y - gy;
        tailf[2] = si.z;
        tailf[3] = si.w;
    }
    __syncthreads();

    // ---- conv1 5->64 (raw-reshape view: h[c][p] = xkflat[c*32+p]) ----
    for (int idx = tid; idx < 2048; idx += TPB) {
        int o = idx >> 5, p = idx & 31;
        float acc = b1s[o];
        #pragma unroll
        for (int c = 0; c < 5; c++)
            acc = fmaf(W1s[o * 5 + c], xkflat[c * 32 + p], acc);
        h1s[idx] = fmaxf(acc, 0.0f);
    }
    __syncthreads();

    // ---- conv2 64->128 + masked argmax: f32x2 over p-pairs, 4-c blocks ----
    {
        const int to = tid >> 3;           // o base = to*4   (0..31)
        const int tp = (tid & 7) << 2;     // p base          (0..28)
        unsigned long long accp[4][2];     // [oo][p-pair], f32x2 accumulators
        #pragma unroll
        for (int oo = 0; oo < 4; oo++) { accp[oo][0] = 0ull; accp[oo][1] = 0ull; }

        #pragma unroll 2
        for (int cb = 0; cb < 16; cb++) {
            float4 wv[4];                  // wv[oo] = W2[o, 4cb..4cb+3]
            #pragma unroll
            for (int oo = 0; oo < 4; oo++)
                wv[oo] = w2s4[((to << 2) + oo) * (W2S_LD / 4) + cb];
            #pragma unroll
            for (int cc = 0; cc < 4; cc++) {       // c ascending: bit-identical order
                const ulonglong2 hv = *reinterpret_cast<const ulonglong2*>(
                    &h1s[(((cb << 2) + cc) << 5) + tp]);
                #pragma unroll
                for (int oo = 0; oo < 4; oo++) {
                    float wsc = (cc == 0) ? wv[oo].x : (cc == 1) ? wv[oo].y
                              : (cc == 2) ? wv[oo].z : wv[oo].w;
                    unsigned long long wd;
                    asm("mov.b64 %0, {%1, %1};" : "=l"(wd) : "f"(wsc));
                    asm("fma.rn.f32x2 %0, %1, %2, %0;" : "+l"(accp[oo][0]) : "l"(wd), "l"(hv.x));
                    asm("fma.rn.f32x2 %0, %1, %2, %0;" : "+l"(accp[oo][1]) : "l"(wd), "l"(hv.y));
                }
            }
        }

        float acc[4][4];
        #pragma unroll
        for (int oo = 0; oo < 4; oo++) {
            asm("mov.b64 {%0, %1}, %2;" : "=f"(acc[oo][0]), "=f"(acc[oo][1]) : "l"(accp[oo][0]));
            asm("mov.b64 {%0, %1}, %2;" : "=f"(acc[oo][2]), "=f"(acc[oo][3]) : "l"(accp[oo][1]));
        }

        float mk[4];
        #pragma unroll
        for (int pp = 0; pp < 4; pp++) mk[pp] = masksh[tp + pp];

        #pragma unroll
        for (int oo = 0; oo < 4; oo++) {
            int o = (to << 2) + oo;
            float bb = b2s[o];
            float bv = 0.0f;
            int   bp = 0;
            #pragma unroll
            for (int pp = 0; pp < 4; pp++) {
                float v = fmaxf(acc[oo][pp] + bb, 0.0f) * mk[pp];
                if (pp == 0) { bv = v; bp = tp; }
                else if (v > bv) { bv = v; bp = tp + pp; }   // strict > keeps first index
            }
            #pragma unroll
            for (int off = 1; off < 8; off <<= 1) {
                float ov = __shfl_xor_sync(0xffffffffu, bv, off);
                int   op = __shfl_xor_sync(0xffffffffu, bp, off);
                if (ov > bv || (ov == bv && op < bp)) { bv = ov; bp = op; }
            }
            if ((tid & 7) == 0) featsh[o] = (float)bp;
        }
    }
    __syncthreads();

    // ---- MLP 132 -> 64 -> 128 -> 64 -> 4 (half-warp float4 dots) ----
    const int hw = lane >> 4;        // half-warp id (0/1)
    const int hl = lane & 15;        // lane within half

    // z1: 64 outputs, 2 per warp per iter
    #pragma unroll
    for (int it = 0; it < 4; it++) {
        int o = (wid << 3) + (it << 1) + hw;
        const float4* wr = (const float4*)(Wd1 + o * 132);
        float4 wa = wr[hl];
        float4 fa = *(const float4*)&featsh[hl << 2];
        float s = wa.x * fa.x;
        s = fmaf(wa.y, fa.y, s); s = fmaf(wa.z, fa.z, s); s = fmaf(wa.w, fa.w, s);
        float4 wb = wr[hl + 16];
        float4 fb = *(const float4*)&featsh[64 + (hl << 2)];
        s = fmaf(wb.x, fb.x, s); s = fmaf(wb.y, fb.y, s);
        s = fmaf(wb.z, fb.z, s); s = fmaf(wb.w, fb.w, s);
        if (hl == 0) {
            float4 wc = wr[32];
            float4 fc = *(const float4*)tailf;
            s = fmaf(wc.x, fc.x, s); s = fmaf(wc.y, fc.y, s);
            s = fmaf(wc.z, fc.z, s); s = fmaf(wc.w, fc.w, s);
        }
        #pragma unroll
        for (int off = 8; off; off >>= 1) s += __shfl_xor_sync(0xffffffffu, s, off);
        if (hl == 0) z1s[o] = fmaxf(s + bd1[o], 0.0f);
    }
    __syncthreads();

    // z2: 128 outputs, 2 per warp per iter
    #pragma unroll
    for (int it = 0; it < 8; it++) {
        int o = (wid << 4) + (it << 1) + hw;
        float4 w = ((const float4*)(Wd2 + (o << 6)))[hl];
        float4 z = ((const float4*)z1s)[hl];
        float s = w.x * z.x;
        s = fmaf(w.y, z.y, s); s = fmaf(w.z, z.z, s); s = fmaf(w.w, z.w, s);
        #pragma unroll
        for (int off = 8; off; off >>= 1) s += __shfl_xor_sync(0xffffffffu, s, off);
        if (hl == 0) z2s[o] = fmaxf(s + bd2[o], 0.0f);
    }
    __syncthreads();

    // z3: 64 outputs, 2 per warp per iter (128 inputs = two float4 passes)
    #pragma unroll
    for (int it = 0; it < 4; it++) {
        int o = (wid << 3) + (it << 1) + hw;
        const float4* wr = (const float4*)(Wd3 + (o << 7));
        float4 wa = wr[hl];
        float4 za = ((const float4*)z2s)[hl];
        float s = wa.x * za.x;
        s = fmaf(wa.y, za.y, s); s = fmaf(wa.z, za.z, s); s = fmaf(wa.w, za.w, s);
        float4 wb = wr[hl + 16];
        float4 zb = ((const float4*)z2s)[hl + 16];
        s = fmaf(wb.x, zb.x, s); s = fmaf(wb.y, zb.y, s);
        s = fmaf(wb.z, zb.z, s); s = fmaf(wb.w, zb.w, s);
        #pragma unroll
        for (int off = 8; off; off >>= 1) s += __shfl_xor_sync(0xffffffffu, s, off);
        if (hl == 0) z3s[o] = fmaxf(s + bd3[o], 0.0f);
    }
    __syncthreads();

    // z4: 4 outputs on warps 0-1
    if (wid < 2) {
        int o = (wid << 1) + hw;
        float4 w = ((const float4*)(Wd4 + (o << 6)))[hl];
        float4 z = ((const float4*)z3s)[hl];
        float s = w.x * z.x;
        s = fmaf(w.y, z.y, s); s = fmaf(w.z, z.z, s); s = fmaf(w.w, z.w, s);
        #pragma unroll
        for (int off = 8; off; off >>= 1) s += __shfl_xor_sync(0xffffffffu, s, off);
        if (hl == 0) z4s[o] = s + bd4[o];
    }
    __syncthreads();

    // ---- gains + control output ----
    if (tid == 0) {
        float k0 = 2.0f / (1.0f + expf(-z4s[0])) + 0.2f;
        float k1 = 2.0f / (1.0f + expf(-z4s[1])) + 0.2f;
        float k2 = 2.0f / (1.0f + expf(-z4s[2])) + 0.2f;
        float k3 = 2.0f / (1.0f + expf(-z4s[3])) + 0.2f;
        float rx = tailf[0], ry = tailf[1];
        float v2 = tailf[2], v3 = tailf[3];
        out[2 * i + 0] = -(k0 * rx + k1 * v2);
        out[2 * i + 1] = -(k2 * ry + k3 * v3);
    }
}

extern "C" void kernel_launch(void* const* d_in, const int* in_sizes, int n_in,
                              void* d_out, int out_size)
{
    (void)in_sizes; (void)n_in; (void)out_size;
    controller_kernel<<<N_AGENTS, TPB>>>(
        (const float4*)d_in[0],  (const float*)d_in[1],
        (const float*)d_in[2],   (const float*)d_in[3],
        (const float*)d_in[4],   (const float*)d_in[5],
        (const float*)d_in[6],   (const float*)d_in[7],
        (const float*)d_in[8],   (const float*)d_in[9],
        (const float*)d_in[10],  (const float*)d_in[11],
        (const float*)d_in[12],  (const float*)d_in[13],
        (float*)d_out);
}

// round 9
// speedup vs baseline: 4.0409x; 1.0604x over previous
#include <cuda_runtime.h>

#define N_AGENTS 4096
#define TPB 256
#define JPT 16          // 4096/256 candidates per thread
#define TOPK 32

// ---- static smem layout (byte offsets), phase-disjoint aliases ----
#define OFF_W2S   0        // f32[128*64] 32768B, XOR-swizzled rows (conv2)
                           //   alias: sorted keys u32[16][256] 16384B (selection)
#define OFF_Z1    0        //   alias: f32[64]  (post-conv2)
#define OFF_Z2    256      //   alias: f32[128]
#define OFF_Z3    768      //   alias: f32[64]
#define OFF_Z4    1024     //   alias: f32[4]
#define OFF_H1S   32768    // f32[64*32] 8192B (conv phases)
#define OFF_SKEY  32768    //   alias: u64[256] 2048B (merge, pre-conv1)
#define OFF_W1S   40960    // f32[320] 1280B
#define OFF_B1S   42240    // f32[64]  256B
#define OFF_B2S   42496    // f32[128] 512B
#define OFF_XK    43008    // f32[160] 640B  (alias: featsh[0..127] post-conv1)
#define OFF_MASK  43648    // f32[32]  128B
#define OFF_SEL   43776    // u32[32]  128B
#define OFF_TAIL  43904    // f32[4]   16B   (rel.x, rel.y, v2, v3)
#define SMEM_TOTAL 43920

#define KEY_BIAS 0x3C000000u

__global__ __launch_bounds__(TPB, 5)
void controller_kernel(
    const float4* __restrict__ states4,   // [N,4]
    const float*  __restrict__ goals,     // [N,2]
    const float*  __restrict__ W1,  const float* __restrict__ b1,
    const float*  __restrict__ W2,  const float* __restrict__ b2,
    const float*  __restrict__ Wd1, const float* __restrict__ bd1,
    const float*  __restrict__ Wd2, const float* __restrict__ bd2,
    const float*  __restrict__ Wd3, const float* __restrict__ bd3,
    const float*  __restrict__ Wd4, const float* __restrict__ bd4,
    float* __restrict__ out)              // [N,2]
{
    __shared__ __align__(16) char smem[SMEM_TOTAL];
    float4*             w2s4    = (float4*)(smem + OFF_W2S);
    unsigned*           sortbuf = (unsigned*)(smem + OFF_W2S);    // alias (selection)
    float*              h1s     = (float*)(smem + OFF_H1S);
    unsigned long long* skey    = (unsigned long long*)(smem + OFF_SKEY);
    float*              W1s     = (float*)(smem + OFF_W1S);
    float*              b1s     = (float*)(smem + OFF_B1S);
    float*              b2s     = (float*)(smem + OFF_B2S);
    float*              xkflat  = (float*)(smem + OFF_XK);
    float*              featsh  = (float*)(smem + OFF_XK);        // alias (post-conv1)
    float*              masksh  = (float*)(smem + OFF_MASK);
    unsigned*           selsh   = (unsigned*)(smem + OFF_SEL);
    float*              tailf   = (float*)(smem + OFF_TAIL);
    float*              z1s     = (float*)(smem + OFF_Z1);
    float*              z2s     = (float*)(smem + OFF_Z2);
    float*              z3s     = (float*)(smem + OFF_Z3);
    float*              z4s     = (float*)(smem + OFF_Z4);

    const int tid  = threadIdx.x;
    const int i    = blockIdx.x;
    const int lane = tid & 31;
    const int wid  = tid >> 5;

    const float4 si = states4[i];

    // ---- phase A: planar distances -> exact u32 keys (monotone in (d, k)) ----
    unsigned key[JPT];
    {
        const float2* stxy = (const float2*)states4;
        #pragma unroll
        for (int k = 0; k < JPT; k++) {
            int j = tid + (k << 8);
            float2 sj = stxy[2 * j];
            float dx = si.x - sj.x;
            float dy = si.y - sj.y;
            float d  = sqrtf(dx * dx + dy * dy + 1e-4f);   // identical to ref path
            key[k] = ((__float_as_uint(d) - KEY_BIAS) << 4) | (unsigned)k;
        }
    }

    // ---- per-thread Batcher odd-even mergesort of 16 keys (registers, 63 CEs) ----
    #pragma unroll
    for (int p = 1; p < 16; p <<= 1) {
        #pragma unroll
        for (int q = p; q > 0; q >>= 1) {
            #pragma unroll
            for (int jj = (q & (p - 1)); jj + q < 16; jj += (q << 1)) {
                #pragma unroll
                for (int ii = 0; ii < q; ii++) {
                    if (ii + jj + q < 16 &&
                        ((ii + jj) / (p << 1) == (ii + jj + q) / (p << 1))) {
                        unsigned a = key[ii + jj], b = key[ii + jj + q];
                        key[ii + jj]     = umin(a, b);
                        key[ii + jj + q] = umax(a, b);
                    }
                }
            }
        }
    }
    // spill sorted column to smem (own column only -> warp-sync safe, no barrier)
    #pragma unroll
    for (int k = 0; k < 16; k++) sortbuf[(k << 8) + tid] = key[k];

    // ---- stage 1: per-warp exact top-32, REDUX tournament ----
    unsigned winkey = 0;
    int      winlane = 0;
    {
        unsigned cur = key[0];
        int head = 1;
        #pragma unroll
        for (int r = 0; r < TOPK; r++) {
            unsigned g = __reduce_min_sync(0xffffffffu, cur);
            unsigned mm = __ballot_sync(0xffffffffu, cur == g);
            int l = __ffs(mm) - 1;          // lowest lane = lowest j on key ties
            if (lane == r) { winkey = g; winlane = l; }
            if (lane == l) {                // winner pops next from its sorted list
                cur = (head < 16) ? sortbuf[(head << 8) + tid] : 0xffffffffu;
                head++;
            }
        }
    }
    // publish rank-`lane` winner as global u64 key (d_bits<<32 | j)
    {
        unsigned dbits = (winkey >> 4) + KEY_BIAS;
        unsigned j = (unsigned)((wid << 5) + winlane) + ((winkey & 15u) << 8);
        skey[tid] = (((unsigned long long)dbits) << 32) | j;
    }
    __syncthreads();

    // ---- merge phase: stage weights (overlaps LDS chains) + rank-merge ----
    for (int t = tid; t < 320; t += TPB) W1s[t] = W1[t];
    if (tid < 64)  b1s[tid] = b1[tid];
    if (tid < 128) b2s[tid] = b2[tid];
    {
        const float4* W2v = (const float4*)W2;     // [128][16] float4
        #pragma unroll
        for (int t = tid; t < 2048; t += TPB) {
            int o = t >> 4, cb = t & 15;
            // XOR swizzle: slot = cb ^ (to & 7), to = o >> 2  -> conflict-free reads, 0B pad
            w2s4[(o << 4) + (cb ^ ((o >> 2) & 7))] = W2v[t];
        }
    }
    {
        unsigned long long k64 = skey[tid];
        int rank = lane;                           // position in own sorted list
        #pragma unroll
        for (int ww = 0; ww < 8; ww++) {
            if (ww == wid) continue;
            const unsigned long long* arr = skey + ww * 32;
            int pos = 0;
            #pragma unroll
            for (int s = 16; s; s >>= 1)
                pos += (arr[pos + s - 1] < k64) ? s : 0;   // count strictly-less
            rank += pos;
        }
        if (rank < TOPK) selsh[rank] = (unsigned)(k64 & 0xffffffffu);
    }
    __syncthreads();

    // ---- gather xk rows + obs mask + tail features ----
    if (tid < TOPK) {
        int j = (int)selsh[tid];
        float4 sj = states4[j];
        float dx = si.x - sj.x;
        float dy = si.y - sj.y;
        xkflat[tid * 5 + 0] = dx;
        xkflat[tid * 5 + 1] = dy;
        xkflat[tid * 5 + 2] = si.z - sj.z;
        xkflat[tid * 5 + 3] = si.w - sj.w;
        xkflat[tid * 5 + 4] = (j == i) ? 1.0f : 0.0f;
        masksh[tid] = (sqrtf(dx * dx + dy * dy) < 1.0f) ? 1.0f : 0.0f;
    }
    if (tid == 0) {
        float gx = goals[2 * i], gy = goals[2 * i + 1];
        tailf[0] = si.x - gx;
        tailf[1] = si.y - gy;
        tailf[2] = si.z;
        tailf[3] = si.w;
    }
    __syncthreads();

    // ---- conv1 5->64 (raw-reshape view: h[c][p] = xkflat[c*32+p]) ----
    for (int idx = tid; idx < 2048; idx += TPB) {
        int o = idx >> 5, p = idx & 31;
        float acc = b1s[o];
        #pragma unroll
        for (int c = 0; c < 5; c++)
            acc = fmaf(W1s[o * 5 + c], xkflat[c * 32 + p], acc);
        h1s[idx] = fmaxf(acc, 0.0f);
    }
    __syncthreads();

    // ---- conv2 64->128 + masked argmax: f32x2 over p-pairs, 4-c blocks ----
    {
        const int to = tid >> 3;           // o base = to*4   (0..31)
        const int tp = (tid & 7) << 2;     // p base          (0..28)
        const int sw = to & 7;             // XOR-swizzle slot key for this thread
        unsigned long long accp[4][2];     // [oo][p-pair], f32x2 accumulators
        #pragma unroll
        for (int oo = 0; oo < 4; oo++) { accp[oo][0] = 0ull; accp[oo][1] = 0ull; }

        #pragma unroll 2
        for (int cb = 0; cb < 16; cb++) {
            float4 wv[4];                  // wv[oo] = W2[o, 4cb..4cb+3]
            #pragma unroll
            for (int oo = 0; oo < 4; oo++)
                wv[oo] = w2s4[(((to << 2) + oo) << 4) + (cb ^ sw)];
            #pragma unroll
            for (int cc = 0; cc < 4; cc++) {       // c ascending: bit-identical order
                const ulonglong2 hv = *reinterpret_cast<const ulonglong2*>(
                    &h1s[(((cb << 2) + cc) << 5) + tp]);
                #pragma unroll
                for (int oo = 0; oo < 4; oo++) {
                    float wsc = (cc == 0) ? wv[oo].x : (cc == 1) ? wv[oo].y
                              : (cc == 2) ? wv[oo].z : wv[oo].w;
                    unsigned long long wd;
                    asm("mov.b64 %0, {%1, %1};" : "=l"(wd) : "f"(wsc));
                    asm("fma.rn.f32x2 %0, %1, %2, %0;" : "+l"(accp[oo][0]) : "l"(wd), "l"(hv.x));
                    asm("fma.rn.f32x2 %0, %1, %2, %0;" : "+l"(accp[oo][1]) : "l"(wd), "l"(hv.y));
                }
            }
        }

        float acc[4][4];
        #pragma unroll
        for (int oo = 0; oo < 4; oo++) {
            asm("mov.b64 {%0, %1}, %2;" : "=f"(acc[oo][0]), "=f"(acc[oo][1]) : "l"(accp[oo][0]));
            asm("mov.b64 {%0, %1}, %2;" : "=f"(acc[oo][2]), "=f"(acc[oo][3]) : "l"(accp[oo][1]));
        }

        float mk[4];
        #pragma unroll
        for (int pp = 0; pp < 4; pp++) mk[pp] = masksh[tp + pp];

        #pragma unroll
        for (int oo = 0; oo < 4; oo++) {
            int o = (to << 2) + oo;
            float bb = b2s[o];
            float bv = 0.0f;
            int   bp = 0;
            #pragma unroll
            for (int pp = 0; pp < 4; pp++) {
                float v = fmaxf(acc[oo][pp] + bb, 0.0f) * mk[pp];
                if (pp == 0) { bv = v; bp = tp; }
                else if (v > bv) { bv = v; bp = tp + pp; }   // strict > keeps first index
            }
            #pragma unroll
            for (int off = 1; off < 8; off <<= 1) {
                float ov = __shfl_xor_sync(0xffffffffu, bv, off);
                int   op = __shfl_xor_sync(0xffffffffu, bp, off);
                if (ov > bv || (ov == bv && op < bp)) { bv = ov; bp = op; }
            }
            if ((tid & 7) == 0) featsh[o] = (float)bp;
        }
    }
    __syncthreads();

    // ---- MLP 132 -> 64 -> 128 -> 64 -> 4 (half-warp float4 dots) ----
    const int hw = lane >> 4;        // half-warp id (0/1)
    const int hl = lane & 15;        // lane within half

    // z1: 64 outputs, 2 per warp per iter
    #pragma unroll
    for (int it = 0; it < 4; it++) {
        int o = (wid << 3) + (it << 1) + hw;
        const float4* wr = (const float4*)(Wd1 + o * 132);
        float4 wa = wr[hl];
        float4 fa = *(const float4*)&featsh[hl << 2];
        float s = wa.x * fa.x;
        s = fmaf(wa.y, fa.y, s); s = fmaf(wa.z, fa.z, s); s = fmaf(wa.w, fa.w, s);
        float4 wb = wr[hl + 16];
        float4 fb = *(const float4*)&featsh[64 + (hl << 2)];
        s = fmaf(wb.x, fb.x, s); s = fmaf(wb.y, fb.y, s);
        s = fmaf(wb.z, fb.z, s); s = fmaf(wb.w, fb.w, s);
        if (hl == 0) {
            float4 wc = wr[32];
            float4 fc = *(const float4*)tailf;
            s = fmaf(wc.x, fc.x, s); s = fmaf(wc.y, fc.y, s);
            s = fmaf(wc.z, fc.z, s); s = fmaf(wc.w, fc.w, s);
        }
        #pragma unroll
        for (int off = 8; off; off >>= 1) s += __shfl_xor_sync(0xffffffffu, s, off);
        if (hl == 0) z1s[o] = fmaxf(s + bd1[o], 0.0f);
    }
    __syncthreads();

    // z2: 128 outputs, 2 per warp per iter
    #pragma unroll
    for (int it = 0; it < 8; it++) {
        int o = (wid << 4) + (it << 1) + hw;
        float4 w = ((const float4*)(Wd2 + (o << 6)))[hl];
        float4 z = ((const float4*)z1s)[hl];
        float s = w.x * z.x;
        s = fmaf(w.y, z.y, s); s = fmaf(w.z, z.z, s); s = fmaf(w.w, z.w, s);
        #pragma unroll
        for (int off = 8; off; off >>= 1) s += __shfl_xor_sync(0xffffffffu, s, off);
        if (hl == 0) z2s[o] = fmaxf(s + bd2[o], 0.0f);
    }
    __syncthreads();

    // z3: 64 outputs, 2 per warp per iter (128 inputs = two float4 passes)
    #pragma unroll
    for (int it = 0; it < 4; it++) {
        int o = (wid << 3) + (it << 1) + hw;
        const float4* wr = (const float4*)(Wd3 + (o << 7));
        float4 wa = wr[hl];
        float4 za = ((const float4*)z2s)[hl];
        float s = wa.x * za.x;
        s = fmaf(wa.y, za.y, s); s = fmaf(wa.z, za.z, s); s = fmaf(wa.w, za.w, s);
        float4 wb = wr[hl + 16];
        float4 zb = ((const float4*)z2s)[hl + 16];
        s = fmaf(wb.x, zb.x, s); s = fmaf(wb.y, zb.y, s);
        s = fmaf(wb.z, zb.z, s); s = fmaf(wb.w, zb.w, s);
        #pragma unroll
        for (int off = 8; off; off >>= 1) s += __shfl_xor_sync(0xffffffffu, s, off);
        if (hl == 0) z3s[o] = fmaxf(s + bd3[o], 0.0f);
    }
    __syncthreads();

    // z4: 4 outputs on warps 0-1
    if (wid < 2) {
        int o = (wid << 1) + hw;
        float4 w = ((const float4*)(Wd4 + (o << 6)))[hl];
        float4 z = ((const float4*)z3s)[hl];
        float s = w.x * z.x;
        s = fmaf(w.y, z.y, s); s = fmaf(w.z, z.z, s); s = fmaf(w.w, z.w, s);
        #pragma unroll
        for (int off = 8; off; off >>= 1) s += __shfl_xor_sync(0xffffffffu, s, off);
        if (hl == 0) z4s[o] = s + bd4[o];
    }
    __syncthreads();

    // ---- gains + control output ----
    if (tid == 0) {
        float k0 = 2.0f / (1.0f + expf(-z4s[0])) + 0.2f;
        float k1 = 2.0f / (1.0f + expf(-z4s[1])) + 0.2f;
        float k2 = 2.0f / (1.0f + expf(-z4s[2])) + 0.2f;
        float k3 = 2.0f / (1.0f + expf(-z4s[3])) + 0.2f;
        float rx = tailf[0], ry = tailf[1];
        float v2 = tailf[2], v3 = tailf[3];
        out[2 * i + 0] = -(k0 * rx + k1 * v2);
        out[2 * i + 1] = -(k2 * ry + k3 * v3);
    }
}

extern "C" void kernel_launch(void* const* d_in, const int* in_sizes, int n_in,
                              void* d_out, int out_size)
{
    (void)in_sizes; (void)n_in; (void)out_size;
    controller_kernel<<<N_AGENTS, TPB>>>(
        (const float4*)d_in[0],  (const float*)d_in[1],
        (const float*)d_in[2],   (const float*)d_in[3],
        (const float*)d_in[4],   (const float*)d_in[5],
        (const float*)d_in[6],   (const float*)d_in[7],
        (const float*)d_in[8],   (const float*)d_in[9],
        (const float*)d_in[10],  (const float*)d_in[11],
        (const float*)d_in[12],  (const float*)d_in[13],
        (float*)d_out);
}